// round 7
// baseline (speedup 1.0000x reference)
#include <cuda_runtime.h>

// ----------------------------------------------------------------------------
// ControlWhile persistent kernel, R6.
// R5 post-mortem: spills gone (DRAM 25%), but stall-bound: L1=64% from the
// 1:1 LDS:FFMA2 weight stream, occ 25%, issue 23%. R6 register-tiles TWO
// pixels per thread (q and q+NPIX/2): one weight LDS feeds two FFMA2s
// (per-pixel LDS 256->128), two independent accumulator chains (ILP=2),
// half the loop bookkeeping. Peak regs ~95 < 128: no spills.
// ----------------------------------------------------------------------------

#define CIN    3
#define COUT   16
#define HW     147456           // 384*384
#define NPIX   1179648          // 8*HW
#define NPIX2  589824           // NPIX/2
#define NTOT   18874368.0       // NPIX*COUT elements in v
#define THRESH (3.0 * NTOT)     // mean|v| < 3  <=>  sum|v| < 3*NTOT
#define MAX_IT 64
#define MAX_BLOCKS 1024
#define TPB    512

// v, pixel-major packed: g_v[p*8 + j] = f32x2 {chan 2j, chan 2j+1} of pixel p.
__device__ __align__(16) unsigned long long g_v[(size_t)NPIX * 8];
// Per-block |v| partial sums — fully overwritten every phase (replay-safe).
__device__ double g_part[MAX_BLOCKS];
// Grid barrier: count returns to 0; gen monotonic, equality-compared (replay-safe).
__device__ unsigned int g_bar_count;
__device__ volatile unsigned int g_bar_gen;

// ---- packed f32x2 helpers (PTX-only; ptxas won't auto-fuse) ----
__device__ __forceinline__ unsigned long long ffma2(unsigned long long a,
                                                    unsigned long long b,
                                                    unsigned long long c) {
    unsigned long long d;
    asm("fma.rn.f32x2 %0, %1, %2, %3;" : "=l"(d) : "l"(a), "l"(b), "l"(c));
    return d;
}
__device__ __forceinline__ unsigned long long pack2(float lo, float hi) {
    unsigned long long d;
    asm("mov.b64 %0, {%1, %2};" : "=l"(d) : "f"(lo), "f"(hi));
    return d;
}
__device__ __forceinline__ float hadd2(unsigned long long v) {
    float lo, hi;
    asm("mov.b64 {%0, %1}, %2;" : "=f"(lo), "=f"(hi) : "l"(v));
    return lo + hi;
}

// tanh via exp (~1e-7 rel err; NOT tanh.approx whose ~5e-4 error is risky for
// the 1e-3 output threshold after loop amplification). Clamp at 9 exact in fp32.
__device__ __forceinline__ float tanhx(float x) {
    float xc = fminf(fmaxf(x, -9.0f), 9.0f);
    float t  = __expf(xc + xc);
    return __fdividef(t - 1.0f, t + 1.0f);
}

// Software grid barrier (all blocks co-resident; verified at launch).
__device__ __forceinline__ void grid_bar() {
    __syncthreads();
    if (threadIdx.x == 0) {
        __threadfence();
        unsigned g = g_bar_gen;
        unsigned a = atomicAdd(&g_bar_count, 1u);
        if (a == gridDim.x - 1) {
            atomicExch(&g_bar_count, 0u);
            __threadfence();
            g_bar_gen = g + 1;
        } else {
            while (g_bar_gen == g) { __nanosleep(64); }
        }
    }
    __syncthreads();
}

// Block-reduce a float partial into g_part[blockIdx.x] (double).
__device__ __forceinline__ void store_block_partial(float part, double* s_wsum) {
    __syncthreads();
    float v = part;
    #pragma unroll
    for (int o = 16; o > 0; o >>= 1) v += __shfl_xor_sync(0xffffffffu, v, o);
    if ((threadIdx.x & 31) == 0) s_wsum[threadIdx.x >> 5] = (double)v;
    __syncthreads();
    if (threadIdx.x == 0) {
        double s = 0.0;
        #pragma unroll
        for (int i = 0; i < TPB / 32; i++) s += s_wsum[i];
        g_part[blockIdx.x] = s;
    }
}

__global__ void __launch_bounds__(TPB, 1)
control_while_kernel(const float* __restrict__ x,
                     const float* __restrict__ wpre, const float* __restrict__ bpre,
                     const float* __restrict__ wloop, const float* __restrict__ bloop,
                     const float* __restrict__ wsh, const float* __restrict__ bsh,
                     float* __restrict__ out)
{
    // Channel-pair-packed weights: s_w*2[o*8+j] = (w[o][2j], w[o][2j+1]).
    __shared__ unsigned long long s_wpre2[COUT * 2];
    __shared__ unsigned long long s_wsh2[COUT * 8];
    __shared__ unsigned long long s_wl2[COUT * 8];
    __shared__ float s_bpre[COUT], s_bsh[COUT], s_bl[COUT];
    __shared__ double s_wsum[TPB / 32];
    __shared__ double s_pg[MAX_BLOCKS];
    __shared__ double s_bcast;

    {
        int t = threadIdx.x;
        if (t < COUT * 8) {
            int o = t >> 3, j = t & 7;
            s_wsh2[t] = pack2(wsh[o * COUT + 2 * j],   wsh[o * COUT + 2 * j + 1]);
            s_wl2[t]  = pack2(wloop[o * COUT + 2 * j], wloop[o * COUT + 2 * j + 1]);
        }
        if (t < COUT * 2) {
            int o = t >> 1, j = t & 1;
            s_wpre2[t] = (j == 0) ? pack2(wpre[o * CIN], wpre[o * CIN + 1])
                                  : pack2(wpre[o * CIN + 2], 0.0f);
        }
        if (t < COUT) {
            s_bpre[t] = bpre[t]; s_bsh[t] = bsh[t]; s_bl[t] = bloop[t];
        }
    }
    __syncthreads();

    const int gid    = blockIdx.x * TPB + threadIdx.x;
    const int stride = gridDim.x * TPB;

    // Batch decomposition for planar x/out. stride may exceed any sub-extent:
    // rollover is a while-loop (R3 lesson).
    const int b0i = gid / HW;
    const int i0i = gid - b0i * HW;

    // ---- phase 0: pre conv 3->16 (x planar -> v packed), sum|v| ----
    {
        float part = 0.f;
        int b = b0i, i = i0i;
        for (int q = gid; q < NPIX; q += stride) {
            const float* xp = x + (size_t)b * (CIN * HW) + i;
            unsigned long long xin0 = pack2(xp[0], xp[HW]);
            unsigned long long xin1 = pack2(xp[2 * HW], 0.0f);
            unsigned long long vo[8];
            #pragma unroll
            for (int o = 0; o < COUT; o += 2) {
                unsigned long long a0 = pack2(s_bpre[o], 0.0f);
                unsigned long long a1 = pack2(s_bpre[o + 1], 0.0f);
                a0 = ffma2(s_wpre2[2 * o],     xin0, a0);
                a0 = ffma2(s_wpre2[2 * o + 1], xin1, a0);
                a1 = ffma2(s_wpre2[2 * o + 2], xin0, a1);
                a1 = ffma2(s_wpre2[2 * o + 3], xin1, a1);
                float s0 = hadd2(a0), s1 = hadd2(a1);
                part += fabsf(s0) + fabsf(s1);
                vo[o >> 1] = pack2(s0, s1);
            }
            ulonglong2* vp2 = (ulonglong2*)(g_v + (size_t)q * 8);
            vp2[0] = make_ulonglong2(vo[0], vo[1]);
            vp2[1] = make_ulonglong2(vo[2], vo[3]);
            vp2[2] = make_ulonglong2(vo[4], vo[5]);
            vp2[3] = make_ulonglong2(vo[6], vo[7]);
            i += stride;
            while (i >= HW) { i -= HW; b++; }
        }
        store_block_partial(part, s_wsum);
    }
    grid_bar();

    // ---- data-dependent while loop, fully on-device ----
    for (int it = 0; it < MAX_IT; it++) {
        // decide: parallel load of g_part into smem, fixed-order sum by thread
        // 0 -> identical double in every block -> identical branch.
        for (int i = threadIdx.x; i < (int)gridDim.x; i += TPB)
            s_pg[i] = ((volatile double*)g_part)[i];
        __syncthreads();
        if (threadIdx.x == 0) {
            double s = 0.0;
            for (int i = 0; i < (int)gridDim.x; i++) s += s_pg[i];
            s_bcast = s;
        }
        __syncthreads();
        double tot = s_bcast;
        __syncthreads();
        if (!(tot < THRESH)) break;   // NaN-safe, same as jnp semantics

        float part = 0.f;
        // 2-pixel tile: pixels q and q+NPIX2. One weight LDS serves both.
        for (int q = gid; q < NPIX2; q += stride) {
            unsigned long long vpA[8], vpB[8];
            {
                const ulonglong2* pA = (const ulonglong2*)(g_v + (size_t)q * 8);
                const ulonglong2* pB =
                    (const ulonglong2*)(g_v + (size_t)(q + NPIX2) * 8);
                ulonglong2 a0 = pA[0], a1 = pA[1], a2 = pA[2], a3 = pA[3];
                ulonglong2 b0 = pB[0], b1 = pB[1], b2 = pB[2], b3 = pB[3];
                vpA[0]=a0.x; vpA[1]=a0.y; vpA[2]=a1.x; vpA[3]=a1.y;
                vpA[4]=a2.x; vpA[5]=a2.y; vpA[6]=a3.x; vpA[7]=a3.y;
                vpB[0]=b0.x; vpB[1]=b0.y; vpB[2]=b1.x; vpB[3]=b1.y;
                vpB[4]=b2.x; vpB[5]=b2.y; vpB[6]=b3.x; vpB[7]=b3.y;
            }
            // conv w_shared + tanh -> hpA/hpB (channel-pair packed)
            unsigned long long hpA[8], hpB[8];
            #pragma unroll
            for (int o = 0; o < COUT; o += 2) {
                unsigned long long bA0 = pack2(s_bsh[o], 0.0f);
                unsigned long long bA1 = pack2(s_bsh[o + 1], 0.0f);
                unsigned long long aA0 = bA0, aB0 = bA0;
                unsigned long long aA1 = bA1, aB1 = bA1;
                #pragma unroll
                for (int j = 0; j < 8; j++) {
                    unsigned long long w0 = s_wsh2[o * 8 + j];
                    unsigned long long w1 = s_wsh2[(o + 1) * 8 + j];
                    aA0 = ffma2(w0, vpA[j], aA0);
                    aB0 = ffma2(w0, vpB[j], aB0);
                    aA1 = ffma2(w1, vpA[j], aA1);
                    aB1 = ffma2(w1, vpB[j], aB1);
                }
                hpA[o >> 1] = pack2(tanhx(hadd2(aA0)), tanhx(hadd2(aA1)));
                hpB[o >> 1] = pack2(tanhx(hadd2(aB0)), tanhx(hadd2(aB1)));
            }
            // conv w_loop, *10, store packed, accumulate |.|
            ulonglong2* sA = (ulonglong2*)(g_v + (size_t)q * 8);
            ulonglong2* sB = (ulonglong2*)(g_v + (size_t)(q + NPIX2) * 8);
            #pragma unroll
            for (int o = 0; o < COUT; o += 4) {
                unsigned long long b0 = pack2(s_bl[o], 0.0f);
                unsigned long long b1 = pack2(s_bl[o + 1], 0.0f);
                unsigned long long b2 = pack2(s_bl[o + 2], 0.0f);
                unsigned long long b3 = pack2(s_bl[o + 3], 0.0f);
                unsigned long long aA0=b0, aA1=b1, aA2=b2, aA3=b3;
                unsigned long long aB0=b0, aB1=b1, aB2=b2, aB3=b3;
                #pragma unroll
                for (int j = 0; j < 8; j++) {
                    unsigned long long w0 = s_wl2[o * 8 + j];
                    unsigned long long w1 = s_wl2[(o + 1) * 8 + j];
                    unsigned long long w2 = s_wl2[(o + 2) * 8 + j];
                    unsigned long long w3 = s_wl2[(o + 3) * 8 + j];
                    aA0 = ffma2(w0, hpA[j], aA0);  aB0 = ffma2(w0, hpB[j], aB0);
                    aA1 = ffma2(w1, hpA[j], aA1);  aB1 = ffma2(w1, hpB[j], aB1);
                    aA2 = ffma2(w2, hpA[j], aA2);  aB2 = ffma2(w2, hpB[j], aB2);
                    aA3 = ffma2(w3, hpA[j], aA3);  aB3 = ffma2(w3, hpB[j], aB3);
                }
                float sA0 = hadd2(aA0) * 10.0f, sA1 = hadd2(aA1) * 10.0f;
                float sA2 = hadd2(aA2) * 10.0f, sA3 = hadd2(aA3) * 10.0f;
                float sB0 = hadd2(aB0) * 10.0f, sB1 = hadd2(aB1) * 10.0f;
                float sB2 = hadd2(aB2) * 10.0f, sB3 = hadd2(aB3) * 10.0f;
                part += fabsf(sA0) + fabsf(sA1) + fabsf(sA2) + fabsf(sA3)
                      + fabsf(sB0) + fabsf(sB1) + fabsf(sB2) + fabsf(sB3);
                sA[o >> 2] = make_ulonglong2(pack2(sA0, sA1), pack2(sA2, sA3));
                sB[o >> 2] = make_ulonglong2(pack2(sB0, sB1), pack2(sB2, sB3));
            }
        }
        store_block_partial(part, s_wsum);
        grid_bar();
    }

    // ---- final conv w_shared (v packed -> out planar) ----
    {
        int b = b0i, i = i0i;
        for (int q = gid; q < NPIX; q += stride) {
            const ulonglong2* p2 = (const ulonglong2*)(g_v + (size_t)q * 8);
            ulonglong2 t0 = p2[0], t1 = p2[1], t2 = p2[2], t3 = p2[3];
            unsigned long long vp[8] = {t0.x, t0.y, t1.x, t1.y,
                                        t2.x, t2.y, t3.x, t3.y};
            float* op = out + (size_t)b * (COUT * HW) + i;
            #pragma unroll
            for (int o = 0; o < COUT; o++) {
                unsigned long long a = pack2(s_bsh[o], 0.0f);
                #pragma unroll
                for (int j = 0; j < 8; j++) a = ffma2(s_wsh2[o * 8 + j], vp[j], a);
                op[(size_t)o * HW] = hadd2(a);
            }
            i += stride;
            while (i >= HW) { i -= HW; b++; }
        }
    }
}

extern "C" void kernel_launch(void* const* d_in, const int* in_sizes, int n_in,
                              void* d_out, int out_size) {
    const float* x     = (const float*)d_in[0];
    const float* wpre  = (const float*)d_in[1];
    const float* bpre  = (const float*)d_in[2];
    const float* wloop = (const float*)d_in[3];
    const float* bloop = (const float*)d_in[4];
    const float* wsh   = (const float*)d_in[5];
    const float* bsh   = (const float*)d_in[6];
    (void)in_sizes; (void)n_in; (void)out_size;

    int dev = 0;
    cudaGetDevice(&dev);
    int sms = 0;
    cudaDeviceGetAttribute(&sms, cudaDevAttrMultiProcessorCount, dev);
    if (sms < 1) sms = 148;

    // Co-residency verified, not assumed: barrier is deadlock-free iff
    // gridDim <= sms * blocksPerSM.
    int occ = 0;
    cudaOccupancyMaxActiveBlocksPerMultiprocessor(&occ, control_while_kernel,
                                                  TPB, 0);
    if (occ < 1) occ = 1;
    long long want = (long long)sms * occ;
    int blocks = (want > MAX_BLOCKS) ? MAX_BLOCKS : (int)want;

    control_while_kernel<<<blocks, TPB>>>(x, wpre, bpre, wloop, bloop, wsh, bsh,
                                          (float*)d_out);
}

// round 10
// speedup vs baseline: 1.5581x; 1.5581x over previous
#include <cuda_runtime.h>

// ----------------------------------------------------------------------------
// ControlWhile persistent kernel, R7.
// R6 post-mortem: 2-pixel tile spilled at TPB=512 (128-reg hard cap; real peak
// ~150 regs) -> R4-style local-memory DRAM storm. R7 keeps the 2-pixel tile
// (halves the LDS weight stream that bounded R5) but at TPB=256, where
// launch_bounds(256,1) allows 255 regs/thread: no spills, occ still 1 blk/SM.
// ----------------------------------------------------------------------------

#define CIN    3
#define COUT   16
#define HW     147456           // 384*384
#define NPIX   1179648          // 8*HW
#define NPIX2  589824           // NPIX/2
#define NTOT   18874368.0       // NPIX*COUT elements in v
#define THRESH (3.0 * NTOT)     // mean|v| < 3  <=>  sum|v| < 3*NTOT
#define MAX_IT 64
#define MAX_BLOCKS 1024
#define TPB    256

// v, pixel-major packed: g_v[p*8 + j] = f32x2 {chan 2j, chan 2j+1} of pixel p.
__device__ __align__(16) unsigned long long g_v[(size_t)NPIX * 8];
// Per-block |v| partial sums — fully overwritten every phase (replay-safe).
__device__ double g_part[MAX_BLOCKS];
// Grid barrier: count returns to 0; gen monotonic, equality-compared (replay-safe).
__device__ unsigned int g_bar_count;
__device__ volatile unsigned int g_bar_gen;

// ---- packed f32x2 helpers (PTX-only; ptxas won't auto-fuse) ----
__device__ __forceinline__ unsigned long long ffma2(unsigned long long a,
                                                    unsigned long long b,
                                                    unsigned long long c) {
    unsigned long long d;
    asm("fma.rn.f32x2 %0, %1, %2, %3;" : "=l"(d) : "l"(a), "l"(b), "l"(c));
    return d;
}
__device__ __forceinline__ unsigned long long pack2(float lo, float hi) {
    unsigned long long d;
    asm("mov.b64 %0, {%1, %2};" : "=l"(d) : "f"(lo), "f"(hi));
    return d;
}
__device__ __forceinline__ float hadd2(unsigned long long v) {
    float lo, hi;
    asm("mov.b64 {%0, %1}, %2;" : "=f"(lo), "=f"(hi) : "l"(v));
    return lo + hi;
}

// tanh via exp (~1e-7 rel err; NOT tanh.approx whose ~5e-4 error is risky for
// the data-dependent trip count). Clamp at 9 exact in fp32.
__device__ __forceinline__ float tanhx(float x) {
    float xc = fminf(fmaxf(x, -9.0f), 9.0f);
    float t  = __expf(xc + xc);
    return __fdividef(t - 1.0f, t + 1.0f);
}

// Software grid barrier (all blocks co-resident; verified at launch).
__device__ __forceinline__ void grid_bar() {
    __syncthreads();
    if (threadIdx.x == 0) {
        __threadfence();
        unsigned g = g_bar_gen;
        unsigned a = atomicAdd(&g_bar_count, 1u);
        if (a == gridDim.x - 1) {
            atomicExch(&g_bar_count, 0u);
            __threadfence();
            g_bar_gen = g + 1;
        } else {
            while (g_bar_gen == g) { __nanosleep(64); }
        }
    }
    __syncthreads();
}

// Block-reduce a float partial into g_part[blockIdx.x] (double).
__device__ __forceinline__ void store_block_partial(float part, double* s_wsum) {
    __syncthreads();
    float v = part;
    #pragma unroll
    for (int o = 16; o > 0; o >>= 1) v += __shfl_xor_sync(0xffffffffu, v, o);
    if ((threadIdx.x & 31) == 0) s_wsum[threadIdx.x >> 5] = (double)v;
    __syncthreads();
    if (threadIdx.x == 0) {
        double s = 0.0;
        #pragma unroll
        for (int i = 0; i < TPB / 32; i++) s += s_wsum[i];
        g_part[blockIdx.x] = s;
    }
}

__global__ void __launch_bounds__(TPB, 1)
control_while_kernel(const float* __restrict__ x,
                     const float* __restrict__ wpre, const float* __restrict__ bpre,
                     const float* __restrict__ wloop, const float* __restrict__ bloop,
                     const float* __restrict__ wsh, const float* __restrict__ bsh,
                     float* __restrict__ out)
{
    // Channel-pair-packed weights: s_w*2[o*8+j] = (w[o][2j], w[o][2j+1]).
    __shared__ unsigned long long s_wpre2[COUT * 2];
    __shared__ unsigned long long s_wsh2[COUT * 8];
    __shared__ unsigned long long s_wl2[COUT * 8];
    __shared__ float s_bpre[COUT], s_bsh[COUT], s_bl[COUT];
    __shared__ double s_wsum[TPB / 32];
    __shared__ double s_pg[MAX_BLOCKS];
    __shared__ double s_bcast;

    {
        int t = threadIdx.x;
        if (t < COUT * 8) {
            int o = t >> 3, j = t & 7;
            s_wsh2[t] = pack2(wsh[o * COUT + 2 * j],   wsh[o * COUT + 2 * j + 1]);
            s_wl2[t]  = pack2(wloop[o * COUT + 2 * j], wloop[o * COUT + 2 * j + 1]);
        }
        if (t < COUT * 2) {
            int o = t >> 1, j = t & 1;
            s_wpre2[t] = (j == 0) ? pack2(wpre[o * CIN], wpre[o * CIN + 1])
                                  : pack2(wpre[o * CIN + 2], 0.0f);
        }
        if (t < COUT) {
            s_bpre[t] = bpre[t]; s_bsh[t] = bsh[t]; s_bl[t] = bloop[t];
        }
    }
    __syncthreads();

    const int gid    = blockIdx.x * TPB + threadIdx.x;
    const int stride = gridDim.x * TPB;

    // Batch decomposition for planar x/out. stride may exceed any sub-extent:
    // rollover is a while-loop (R3 lesson).
    const int b0i = gid / HW;
    const int i0i = gid - b0i * HW;

    // ---- phase 0: pre conv 3->16 (x planar -> v packed), sum|v| ----
    {
        float part = 0.f;
        int b = b0i, i = i0i;
        for (int q = gid; q < NPIX; q += stride) {
            const float* xp = x + (size_t)b * (CIN * HW) + i;
            unsigned long long xin0 = pack2(xp[0], xp[HW]);
            unsigned long long xin1 = pack2(xp[2 * HW], 0.0f);
            unsigned long long vo[8];
            #pragma unroll
            for (int o = 0; o < COUT; o += 2) {
                unsigned long long a0 = pack2(s_bpre[o], 0.0f);
                unsigned long long a1 = pack2(s_bpre[o + 1], 0.0f);
                a0 = ffma2(s_wpre2[2 * o],     xin0, a0);
                a0 = ffma2(s_wpre2[2 * o + 1], xin1, a0);
                a1 = ffma2(s_wpre2[2 * o + 2], xin0, a1);
                a1 = ffma2(s_wpre2[2 * o + 3], xin1, a1);
                float s0 = hadd2(a0), s1 = hadd2(a1);
                part += fabsf(s0) + fabsf(s1);
                vo[o >> 1] = pack2(s0, s1);
            }
            ulonglong2* vp2 = (ulonglong2*)(g_v + (size_t)q * 8);
            vp2[0] = make_ulonglong2(vo[0], vo[1]);
            vp2[1] = make_ulonglong2(vo[2], vo[3]);
            vp2[2] = make_ulonglong2(vo[4], vo[5]);
            vp2[3] = make_ulonglong2(vo[6], vo[7]);
            i += stride;
            while (i >= HW) { i -= HW; b++; }
        }
        store_block_partial(part, s_wsum);
    }
    grid_bar();

    // ---- data-dependent while loop, fully on-device ----
    for (int it = 0; it < MAX_IT; it++) {
        // decide: parallel load of g_part into smem, fixed-order sum by thread
        // 0 -> identical double in every block -> identical branch.
        for (int i = threadIdx.x; i < (int)gridDim.x; i += TPB)
            s_pg[i] = ((volatile double*)g_part)[i];
        __syncthreads();
        if (threadIdx.x == 0) {
            double s = 0.0;
            for (int i = 0; i < (int)gridDim.x; i++) s += s_pg[i];
            s_bcast = s;
        }
        __syncthreads();
        double tot = s_bcast;
        __syncthreads();
        if (!(tot < THRESH)) break;   // NaN-safe, same as jnp semantics

        float part = 0.f;
        // 2-pixel tile: pixels q and q+NPIX2. One weight LDS serves both.
        for (int q = gid; q < NPIX2; q += stride) {
            unsigned long long vpA[8], vpB[8];
            {
                const ulonglong2* pA = (const ulonglong2*)(g_v + (size_t)q * 8);
                const ulonglong2* pB =
                    (const ulonglong2*)(g_v + (size_t)(q + NPIX2) * 8);
                ulonglong2 a0 = pA[0], a1 = pA[1], a2 = pA[2], a3 = pA[3];
                ulonglong2 b0 = pB[0], b1 = pB[1], b2 = pB[2], b3 = pB[3];
                vpA[0]=a0.x; vpA[1]=a0.y; vpA[2]=a1.x; vpA[3]=a1.y;
                vpA[4]=a2.x; vpA[5]=a2.y; vpA[6]=a3.x; vpA[7]=a3.y;
                vpB[0]=b0.x; vpB[1]=b0.y; vpB[2]=b1.x; vpB[3]=b1.y;
                vpB[4]=b2.x; vpB[5]=b2.y; vpB[6]=b3.x; vpB[7]=b3.y;
            }
            // conv w_shared + tanh -> hpA/hpB (channel-pair packed)
            unsigned long long hpA[8], hpB[8];
            #pragma unroll
            for (int o = 0; o < COUT; o += 2) {
                unsigned long long bb0 = pack2(s_bsh[o], 0.0f);
                unsigned long long bb1 = pack2(s_bsh[o + 1], 0.0f);
                unsigned long long aA0 = bb0, aB0 = bb0;
                unsigned long long aA1 = bb1, aB1 = bb1;
                #pragma unroll
                for (int j = 0; j < 8; j++) {
                    unsigned long long w0 = s_wsh2[o * 8 + j];
                    unsigned long long w1 = s_wsh2[(o + 1) * 8 + j];
                    aA0 = ffma2(w0, vpA[j], aA0);
                    aB0 = ffma2(w0, vpB[j], aB0);
                    aA1 = ffma2(w1, vpA[j], aA1);
                    aB1 = ffma2(w1, vpB[j], aB1);
                }
                hpA[o >> 1] = pack2(tanhx(hadd2(aA0)), tanhx(hadd2(aA1)));
                hpB[o >> 1] = pack2(tanhx(hadd2(aB0)), tanhx(hadd2(aB1)));
            }
            // conv w_loop, *10, store packed, accumulate |.|
            ulonglong2* sA = (ulonglong2*)(g_v + (size_t)q * 8);
            ulonglong2* sB = (ulonglong2*)(g_v + (size_t)(q + NPIX2) * 8);
            #pragma unroll
            for (int o = 0; o < COUT; o += 4) {
                unsigned long long b0 = pack2(s_bl[o], 0.0f);
                unsigned long long b1 = pack2(s_bl[o + 1], 0.0f);
                unsigned long long b2 = pack2(s_bl[o + 2], 0.0f);
                unsigned long long b3 = pack2(s_bl[o + 3], 0.0f);
                unsigned long long aA0=b0, aA1=b1, aA2=b2, aA3=b3;
                unsigned long long aB0=b0, aB1=b1, aB2=b2, aB3=b3;
                #pragma unroll
                for (int j = 0; j < 8; j++) {
                    unsigned long long w0 = s_wl2[o * 8 + j];
                    unsigned long long w1 = s_wl2[(o + 1) * 8 + j];
                    unsigned long long w2 = s_wl2[(o + 2) * 8 + j];
                    unsigned long long w3 = s_wl2[(o + 3) * 8 + j];
                    aA0 = ffma2(w0, hpA[j], aA0);  aB0 = ffma2(w0, hpB[j], aB0);
                    aA1 = ffma2(w1, hpA[j], aA1);  aB1 = ffma2(w1, hpB[j], aB1);
                    aA2 = ffma2(w2, hpA[j], aA2);  aB2 = ffma2(w2, hpB[j], aB2);
                    aA3 = ffma2(w3, hpA[j], aA3);  aB3 = ffma2(w3, hpB[j], aB3);
                }
                float sA0 = hadd2(aA0) * 10.0f, sA1 = hadd2(aA1) * 10.0f;
                float sA2 = hadd2(aA2) * 10.0f, sA3 = hadd2(aA3) * 10.0f;
                float sB0 = hadd2(aB0) * 10.0f, sB1 = hadd2(aB1) * 10.0f;
                float sB2 = hadd2(aB2) * 10.0f, sB3 = hadd2(aB3) * 10.0f;
                part += fabsf(sA0) + fabsf(sA1) + fabsf(sA2) + fabsf(sA3)
                      + fabsf(sB0) + fabsf(sB1) + fabsf(sB2) + fabsf(sB3);
                sA[o >> 2] = make_ulonglong2(pack2(sA0, sA1), pack2(sA2, sA3));
                sB[o >> 2] = make_ulonglong2(pack2(sB0, sB1), pack2(sB2, sB3));
            }
        }
        store_block_partial(part, s_wsum);
        grid_bar();
    }

    // ---- final conv w_shared (v packed -> out planar) ----
    {
        int b = b0i, i = i0i;
        for (int q = gid; q < NPIX; q += stride) {
            const ulonglong2* p2 = (const ulonglong2*)(g_v + (size_t)q * 8);
            ulonglong2 t0 = p2[0], t1 = p2[1], t2 = p2[2], t3 = p2[3];
            unsigned long long vp[8] = {t0.x, t0.y, t1.x, t1.y,
                                        t2.x, t2.y, t3.x, t3.y};
            float* op = out + (size_t)b * (COUT * HW) + i;
            #pragma unroll
            for (int o = 0; o < COUT; o++) {
                unsigned long long a = pack2(s_bsh[o], 0.0f);
                #pragma unroll
                for (int j = 0; j < 8; j++) a = ffma2(s_wsh2[o * 8 + j], vp[j], a);
                op[(size_t)o * HW] = hadd2(a);
            }
            i += stride;
            while (i >= HW) { i -= HW; b++; }
        }
    }
}

extern "C" void kernel_launch(void* const* d_in, const int* in_sizes, int n_in,
                              void* d_out, int out_size) {
    const float* x     = (const float*)d_in[0];
    const float* wpre  = (const float*)d_in[1];
    const float* bpre  = (const float*)d_in[2];
    const float* wloop = (const float*)d_in[3];
    const float* bloop = (const float*)d_in[4];
    const float* wsh   = (const float*)d_in[5];
    const float* bsh   = (const float*)d_in[6];
    (void)in_sizes; (void)n_in; (void)out_size;

    int dev = 0;
    cudaGetDevice(&dev);
    int sms = 0;
    cudaDeviceGetAttribute(&sms, cudaDevAttrMultiProcessorCount, dev);
    if (sms < 1) sms = 148;

    // Co-residency verified, not assumed: barrier is deadlock-free iff
    // gridDim <= sms * blocksPerSM.
    int occ = 0;
    cudaOccupancyMaxActiveBlocksPerMultiprocessor(&occ, control_while_kernel,
                                                  TPB, 0);
    if (occ < 1) occ = 1;
    long long want = (long long)sms * occ;
    int blocks = (want > MAX_BLOCKS) ? MAX_BLOCKS : (int)want;

    control_while_kernel<<<blocks, TPB>>>(x, wpre, bpre, wloop, bloop, wsh, bsh,
                                          (float*)d_out);
}

// round 11
// speedup vs baseline: 3.5270x; 2.2637x over previous
#include <cuda_runtime.h>

// ----------------------------------------------------------------------------
// ControlWhile persistent kernel, R8.
// R7 post-mortem: 2-pixel register tiling demands >255 regs -> spills; dead
// end. Rollback to R5 structure (1 pixel/thread, TPB=512) and halve the LDS
// weight stream instead: inner loops consume weights as 16B LDS.128 pairs
// (one shared-load feeds two FFMA2s). L1 wavefront pressure (R5: 64%) and
// issue count drop; register profile unchanged (~95 live, 128 cap).
// ----------------------------------------------------------------------------

#define CIN    3
#define COUT   16
#define HW     147456           // 384*384
#define NPIX   1179648          // 8*HW
#define NTOT   18874368.0       // NPIX*COUT elements in v
#define THRESH (3.0 * NTOT)     // mean|v| < 3  <=>  sum|v| < 3*NTOT
#define MAX_IT 64
#define MAX_BLOCKS 1024
#define TPB    512

// v, pixel-major packed: g_v[p*8 + j] = f32x2 {chan 2j, chan 2j+1} of pixel p.
__device__ __align__(16) unsigned long long g_v[(size_t)NPIX * 8];
// Per-block |v| partial sums — fully overwritten every phase (replay-safe).
__device__ double g_part[MAX_BLOCKS];
// Grid barrier: count returns to 0; gen monotonic, equality-compared (replay-safe).
__device__ unsigned int g_bar_count;
__device__ volatile unsigned int g_bar_gen;

// ---- packed f32x2 helpers (PTX-only; ptxas won't auto-fuse) ----
__device__ __forceinline__ unsigned long long ffma2(unsigned long long a,
                                                    unsigned long long b,
                                                    unsigned long long c) {
    unsigned long long d;
    asm("fma.rn.f32x2 %0, %1, %2, %3;" : "=l"(d) : "l"(a), "l"(b), "l"(c));
    return d;
}
__device__ __forceinline__ unsigned long long pack2(float lo, float hi) {
    unsigned long long d;
    asm("mov.b64 %0, {%1, %2};" : "=l"(d) : "f"(lo), "f"(hi));
    return d;
}
__device__ __forceinline__ float hadd2(unsigned long long v) {
    float lo, hi;
    asm("mov.b64 {%0, %1}, %2;" : "=f"(lo), "=f"(hi) : "l"(v));
    return lo + hi;
}

// tanh = 1 - 2/(e^{2x}+1); ~1e-7 rel err (NOT tanh.approx: ~5e-4 error is
// risky for the data-dependent trip count). Clamp at 9 exact in fp32.
__device__ __forceinline__ float tanhx(float x) {
    float xc = fminf(fmaxf(x, -9.0f), 9.0f);
    float t  = __expf(xc + xc);
    return 1.0f - __fdividef(2.0f, t + 1.0f);
}

// Software grid barrier (all blocks co-resident; verified at launch).
__device__ __forceinline__ void grid_bar() {
    __syncthreads();
    if (threadIdx.x == 0) {
        __threadfence();
        unsigned g = g_bar_gen;
        unsigned a = atomicAdd(&g_bar_count, 1u);
        if (a == gridDim.x - 1) {
            atomicExch(&g_bar_count, 0u);
            __threadfence();
            g_bar_gen = g + 1;
        } else {
            while (g_bar_gen == g) { __nanosleep(64); }
        }
    }
    __syncthreads();
}

// Block-reduce a float partial into g_part[blockIdx.x] (double).
__device__ __forceinline__ void store_block_partial(float part, double* s_wsum) {
    __syncthreads();
    float v = part;
    #pragma unroll
    for (int o = 16; o > 0; o >>= 1) v += __shfl_xor_sync(0xffffffffu, v, o);
    if ((threadIdx.x & 31) == 0) s_wsum[threadIdx.x >> 5] = (double)v;
    __syncthreads();
    if (threadIdx.x == 0) {
        double s = 0.0;
        #pragma unroll
        for (int i = 0; i < TPB / 32; i++) s += s_wsum[i];
        g_part[blockIdx.x] = s;
    }
}

__global__ void __launch_bounds__(TPB, 1)
control_while_kernel(const float* __restrict__ x,
                     const float* __restrict__ wpre, const float* __restrict__ bpre,
                     const float* __restrict__ wloop, const float* __restrict__ bloop,
                     const float* __restrict__ wsh, const float* __restrict__ bsh,
                     float* __restrict__ out)
{
    // Channel-pair-packed weights: s_w*2[o*8+j] = (w[o][2j], w[o][2j+1]).
    // 16B-aligned so (j even) pairs load as a single LDS.128.
    __shared__ __align__(16) unsigned long long s_wpre2[COUT * 2];
    __shared__ __align__(16) unsigned long long s_wsh2[COUT * 8];
    __shared__ __align__(16) unsigned long long s_wl2[COUT * 8];
    __shared__ float s_bpre[COUT], s_bsh[COUT], s_bl[COUT];
    __shared__ double s_wsum[TPB / 32];
    __shared__ double s_pg[MAX_BLOCKS];
    __shared__ double s_bcast;

    {
        int t = threadIdx.x;
        if (t < COUT * 8) {
            int o = t >> 3, j = t & 7;
            s_wsh2[t] = pack2(wsh[o * COUT + 2 * j],   wsh[o * COUT + 2 * j + 1]);
            s_wl2[t]  = pack2(wloop[o * COUT + 2 * j], wloop[o * COUT + 2 * j + 1]);
        }
        if (t < COUT * 2) {
            int o = t >> 1, j = t & 1;
            s_wpre2[t] = (j == 0) ? pack2(wpre[o * CIN], wpre[o * CIN + 1])
                                  : pack2(wpre[o * CIN + 2], 0.0f);
        }
        if (t < COUT) {
            s_bpre[t] = bpre[t]; s_bsh[t] = bsh[t]; s_bl[t] = bloop[t];
        }
    }
    __syncthreads();

    const int gid    = blockIdx.x * TPB + threadIdx.x;
    const int stride = gridDim.x * TPB;

    // Batch decomposition for planar x/out. stride may exceed any sub-extent:
    // rollover is a while-loop (R3 lesson).
    const int b0i = gid / HW;
    const int i0i = gid - b0i * HW;

    // ---- phase 0: pre conv 3->16 (x planar -> v packed), sum|v| ----
    {
        float part = 0.f;
        int b = b0i, i = i0i;
        for (int q = gid; q < NPIX; q += stride) {
            const float* xp = x + (size_t)b * (CIN * HW) + i;
            unsigned long long xin0 = pack2(xp[0], xp[HW]);
            unsigned long long xin1 = pack2(xp[2 * HW], 0.0f);
            unsigned long long vo[8];
            #pragma unroll
            for (int o = 0; o < COUT; o += 2) {
                ulonglong2 w0 = *(const ulonglong2*)&s_wpre2[2 * o];
                ulonglong2 w1 = *(const ulonglong2*)&s_wpre2[2 * o + 2];
                unsigned long long a0 = pack2(s_bpre[o], 0.0f);
                unsigned long long a1 = pack2(s_bpre[o + 1], 0.0f);
                a0 = ffma2(w0.x, xin0, a0);
                a0 = ffma2(w0.y, xin1, a0);
                a1 = ffma2(w1.x, xin0, a1);
                a1 = ffma2(w1.y, xin1, a1);
                float s0 = hadd2(a0), s1 = hadd2(a1);
                part += fabsf(s0) + fabsf(s1);
                vo[o >> 1] = pack2(s0, s1);
            }
            ulonglong2* vp2 = (ulonglong2*)(g_v + (size_t)q * 8);
            vp2[0] = make_ulonglong2(vo[0], vo[1]);
            vp2[1] = make_ulonglong2(vo[2], vo[3]);
            vp2[2] = make_ulonglong2(vo[4], vo[5]);
            vp2[3] = make_ulonglong2(vo[6], vo[7]);
            i += stride;
            while (i >= HW) { i -= HW; b++; }
        }
        store_block_partial(part, s_wsum);
    }
    grid_bar();

    // ---- data-dependent while loop, fully on-device ----
    for (int it = 0; it < MAX_IT; it++) {
        // decide: parallel load of g_part into smem, fixed-order sum by thread
        // 0 -> identical double in every block -> identical branch.
        for (int i = threadIdx.x; i < (int)gridDim.x; i += TPB)
            s_pg[i] = ((volatile double*)g_part)[i];
        __syncthreads();
        if (threadIdx.x == 0) {
            double s = 0.0;
            for (int i = 0; i < (int)gridDim.x; i++) s += s_pg[i];
            s_bcast = s;
        }
        __syncthreads();
        double tot = s_bcast;
        __syncthreads();
        if (!(tot < THRESH)) break;   // NaN-safe, same as jnp semantics

        float part = 0.f;
        // software-pipelined grid-stride: prefetch next pixel while computing
        unsigned long long vp[8];
        {
            const ulonglong2* p2 = (const ulonglong2*)(g_v + (size_t)gid * 8);
            if (gid < NPIX) {
                ulonglong2 t0 = p2[0], t1 = p2[1], t2 = p2[2], t3 = p2[3];
                vp[0]=t0.x; vp[1]=t0.y; vp[2]=t1.x; vp[3]=t1.y;
                vp[4]=t2.x; vp[5]=t2.y; vp[6]=t3.x; vp[7]=t3.y;
            }
        }
        for (int q = gid; q < NPIX; q += stride) {
            unsigned long long vn[8];
            int qn = q + stride;
            if (qn < NPIX) {
                const ulonglong2* p2 = (const ulonglong2*)(g_v + (size_t)qn * 8);
                ulonglong2 t0 = p2[0], t1 = p2[1], t2 = p2[2], t3 = p2[3];
                vn[0]=t0.x; vn[1]=t0.y; vn[2]=t1.x; vn[3]=t1.y;
                vn[4]=t2.x; vn[5]=t2.y; vn[6]=t3.x; vn[7]=t3.y;
            }
            // conv w_shared + tanh -> hp (channel-pair packed).
            // Weights consumed as LDS.128 pairs: one load -> two FFMA2.
            unsigned long long hp[8];
            #pragma unroll
            for (int o = 0; o < COUT; o += 2) {
                unsigned long long a0 = pack2(s_bsh[o], 0.0f);
                unsigned long long a1 = pack2(s_bsh[o + 1], 0.0f);
                #pragma unroll
                for (int j = 0; j < 8; j += 2) {
                    ulonglong2 w0 = *(const ulonglong2*)&s_wsh2[o * 8 + j];
                    ulonglong2 w1 = *(const ulonglong2*)&s_wsh2[(o + 1) * 8 + j];
                    a0 = ffma2(w0.x, vp[j],     a0);
                    a0 = ffma2(w0.y, vp[j + 1], a0);
                    a1 = ffma2(w1.x, vp[j],     a1);
                    a1 = ffma2(w1.y, vp[j + 1], a1);
                }
                hp[o >> 1] = pack2(tanhx(hadd2(a0)), tanhx(hadd2(a1)));
            }
            // conv w_loop, *10, store packed, accumulate |.|
            ulonglong2* vs2 = (ulonglong2*)(g_v + (size_t)q * 8);
            #pragma unroll
            for (int o = 0; o < COUT; o += 4) {
                unsigned long long a0 = pack2(s_bl[o], 0.0f);
                unsigned long long a1 = pack2(s_bl[o + 1], 0.0f);
                unsigned long long a2 = pack2(s_bl[o + 2], 0.0f);
                unsigned long long a3 = pack2(s_bl[o + 3], 0.0f);
                #pragma unroll
                for (int j = 0; j < 8; j += 2) {
                    ulonglong2 w0 = *(const ulonglong2*)&s_wl2[o * 8 + j];
                    ulonglong2 w1 = *(const ulonglong2*)&s_wl2[(o + 1) * 8 + j];
                    ulonglong2 w2 = *(const ulonglong2*)&s_wl2[(o + 2) * 8 + j];
                    ulonglong2 w3 = *(const ulonglong2*)&s_wl2[(o + 3) * 8 + j];
                    a0 = ffma2(w0.x, hp[j], a0);  a0 = ffma2(w0.y, hp[j + 1], a0);
                    a1 = ffma2(w1.x, hp[j], a1);  a1 = ffma2(w1.y, hp[j + 1], a1);
                    a2 = ffma2(w2.x, hp[j], a2);  a2 = ffma2(w2.y, hp[j + 1], a2);
                    a3 = ffma2(w3.x, hp[j], a3);  a3 = ffma2(w3.y, hp[j + 1], a3);
                }
                float s0 = hadd2(a0) * 10.0f, s1 = hadd2(a1) * 10.0f;
                float s2 = hadd2(a2) * 10.0f, s3 = hadd2(a3) * 10.0f;
                part += fabsf(s0) + fabsf(s1) + fabsf(s2) + fabsf(s3);
                vs2[o >> 2] = make_ulonglong2(pack2(s0, s1), pack2(s2, s3));
            }
            #pragma unroll
            for (int j = 0; j < 8; j++) vp[j] = vn[j];
        }
        store_block_partial(part, s_wsum);
        grid_bar();
    }

    // ---- final conv w_shared (v packed -> out planar) ----
    {
        int b = b0i, i = i0i;
        for (int q = gid; q < NPIX; q += stride) {
            const ulonglong2* p2 = (const ulonglong2*)(g_v + (size_t)q * 8);
            ulonglong2 t0 = p2[0], t1 = p2[1], t2 = p2[2], t3 = p2[3];
            unsigned long long vp[8] = {t0.x, t0.y, t1.x, t1.y,
                                        t2.x, t2.y, t3.x, t3.y};
            float* op = out + (size_t)b * (COUT * HW) + i;
            #pragma unroll
            for (int o = 0; o < COUT; o++) {
                unsigned long long a = pack2(s_bsh[o], 0.0f);
                #pragma unroll
                for (int j = 0; j < 8; j += 2) {
                    ulonglong2 w = *(const ulonglong2*)&s_wsh2[o * 8 + j];
                    a = ffma2(w.x, vp[j], a);
                    a = ffma2(w.y, vp[j + 1], a);
                }
                op[(size_t)o * HW] = hadd2(a);
            }
            i += stride;
            while (i >= HW) { i -= HW; b++; }
        }
    }
}

extern "C" void kernel_launch(void* const* d_in, const int* in_sizes, int n_in,
                              void* d_out, int out_size) {
    const float* x     = (const float*)d_in[0];
    const float* wpre  = (const float*)d_in[1];
    const float* bpre  = (const float*)d_in[2];
    const float* wloop = (const float*)d_in[3];
    const float* bloop = (const float*)d_in[4];
    const float* wsh   = (const float*)d_in[5];
    const float* bsh   = (const float*)d_in[6];
    (void)in_sizes; (void)n_in; (void)out_size;

    int dev = 0;
    cudaGetDevice(&dev);
    int sms = 0;
    cudaDeviceGetAttribute(&sms, cudaDevAttrMultiProcessorCount, dev);
    if (sms < 1) sms = 148;

    // Co-residency verified, not assumed: barrier is deadlock-free iff
    // gridDim <= sms * blocksPerSM.
    int occ = 0;
    cudaOccupancyMaxActiveBlocksPerMultiprocessor(&occ, control_while_kernel,
                                                  TPB, 0);
    if (occ < 1) occ = 1;
    long long want = (long long)sms * occ;
    int blocks = (want > MAX_BLOCKS) ? MAX_BLOCKS : (int)want;

    control_while_kernel<<<blocks, TPB>>>(x, wpre, bpre, wloop, bloop, wsh, bsh,
                                          (float*)d_out);
}